// round 14
// baseline (speedup 1.0000x reference)
#include <cuda_runtime.h>
#include <math.h>

#define NN 100000
#define EE 640000
#define DD 128
#define DE 32
#define EPSLN 1e-5f

// ---------------- scratch (static device globals; no runtime alloc) ----------------
__device__ int   g_is64;
__device__ int   g_src[EE];
__device__ int   g_dst[EE];
__device__ int   g_deg[NN];
__device__ float g_invdeg[NN];
__device__ float g_node[NN * DD];       // 51.2 MB
__device__ float g_edge_emb[EE * DD];   // 327.7 MB
__device__ float g_agg[NN * DD];        // 51.2 MB
__device__ float g_segsum[7 * DD];

__device__ __forceinline__ float gelu_exact(float v) {
    return 0.5f * v * (1.0f + erff(v * 0.70710678118654752f));
}

// ---------------- index dtype detection + conversion ----------------
__global__ void k_detect(const int* __restrict__ w) {
    // int64 little-endian: high words (odd positions) are all 0 for values < 2^31.
    int nz = 0;
    for (int i = 1; i < 64; i += 2) nz |= (w[i] != 0);
    g_is64 = nz ? 0 : 1;
}

__global__ void k_convert(const void* __restrict__ ei) {
    int e = blockIdx.x * blockDim.x + threadIdx.x;
    if (e >= EE) return;
    if (g_is64) {
        const long long* p = (const long long*)ei;
        g_src[e] = (int)p[e];
        g_dst[e] = (int)p[EE + e];
    } else {
        const int* p = (const int*)ei;
        g_src[e] = p[e];
        g_dst[e] = p[EE + e];
    }
}

__global__ void k_zero_deg() {
    int i = blockIdx.x * blockDim.x + threadIdx.x;
    if (i < NN) g_deg[i] = 0;
}
__global__ void k_count_deg() {
    int e = blockIdx.x * blockDim.x + threadIdx.x;
    if (e < EE) atomicAdd(&g_deg[g_dst[e]], 1);
}
__global__ void k_invdeg() {
    int n = blockIdx.x * blockDim.x + threadIdx.x;
    if (n < NN) g_invdeg[n] = 1.0f / (float)max(g_deg[n], 1);
}
__global__ void k_zero_agg() {
    int i = blockIdx.x * blockDim.x + threadIdx.x;
    if (i < NN * DD / 4) ((float4*)g_agg)[i] = make_float4(0.f, 0.f, 0.f, 0.f);
}

// ---------------- node embed: node = x @ node_w + node_b ----------------
// C[64][128], K=128. 256 threads, 4x8 register tile per thread.
__global__ void __launch_bounds__(256) k_node_embed(
    const float* __restrict__ x, const float* __restrict__ W, const float* __restrict__ b)
{
    __shared__ float As[64 * 132];
    __shared__ float Ws[16 * 128];
    const int tid = threadIdx.x;
    const int row0 = blockIdx.x * 64;

    for (int i = tid; i < 64 * 32; i += 256) {
        int r = i >> 5, q = i & 31;
        int gr = row0 + r;
        float4 v = (gr < NN) ? ((const float4*)x)[gr * 32 + q] : make_float4(0.f, 0.f, 0.f, 0.f);
        *(float4*)&As[r * 132 + q * 4] = v;
    }

    const int tx = tid & 15, ty = tid >> 4;
    float acc[4][8];
#pragma unroll
    for (int r = 0; r < 4; r++)
#pragma unroll
        for (int c = 0; c < 8; c++) acc[r][c] = 0.f;

    for (int k0 = 0; k0 < 128; k0 += 16) {
        __syncthreads();
        for (int i = tid; i < 512; i += 256)
            ((float4*)Ws)[i] = ((const float4*)W)[k0 * 32 + i];
        __syncthreads();
#pragma unroll
        for (int kk = 0; kk < 16; kk++) {
            float a0 = As[(ty * 4 + 0) * 132 + k0 + kk];
            float a1 = As[(ty * 4 + 1) * 132 + k0 + kk];
            float a2 = As[(ty * 4 + 2) * 132 + k0 + kk];
            float a3 = As[(ty * 4 + 3) * 132 + k0 + kk];
            float4 w0 = *(const float4*)&Ws[kk * 128 + tx * 8];
            float4 w1 = *(const float4*)&Ws[kk * 128 + tx * 8 + 4];
            float wv[8] = {w0.x, w0.y, w0.z, w0.w, w1.x, w1.y, w1.z, w1.w};
#pragma unroll
            for (int c = 0; c < 8; c++) {
                acc[0][c] += a0 * wv[c];
                acc[1][c] += a1 * wv[c];
                acc[2][c] += a2 * wv[c];
                acc[3][c] += a3 * wv[c];
            }
        }
    }
    const int col0 = tx * 8;
    float bb[8];
#pragma unroll
    for (int c = 0; c < 8; c++) bb[c] = __ldg(&b[col0 + c]);
#pragma unroll
    for (int r = 0; r < 4; r++) {
        int gr = row0 + ty * 4 + r;
        if (gr < NN) {
#pragma unroll
            for (int c = 0; c < 8; c++) g_node[gr * 128 + col0 + c] = acc[r][c] + bb[c];
        }
    }
}

// ---------------- edge embed: edge_emb = edge_attr @ edge_w + edge_b (K=32) ----------------
__global__ void __launch_bounds__(256) k_edge_embed(
    const float* __restrict__ ea, const float* __restrict__ W, const float* __restrict__ b)
{
    __shared__ float As[64 * 36];
    __shared__ float Ws[32 * 128];
    const int tid = threadIdx.x;
    const int row0 = blockIdx.x * 64;   // E % 64 == 0

    for (int i = tid; i < 64 * 8; i += 256) {
        int r = i >> 3, q = i & 7;
        *(float4*)&As[r * 36 + q * 4] = ((const float4*)ea)[(row0 + r) * 8 + q];
    }
    for (int i = tid; i < 1024; i += 256)
        ((float4*)Ws)[i] = ((const float4*)W)[i];
    __syncthreads();

    const int tx = tid & 15, ty = tid >> 4;
    float acc[4][8];
#pragma unroll
    for (int r = 0; r < 4; r++)
#pragma unroll
        for (int c = 0; c < 8; c++) acc[r][c] = 0.f;

#pragma unroll
    for (int kk = 0; kk < 32; kk++) {
        float a0 = As[(ty * 4 + 0) * 36 + kk];
        float a1 = As[(ty * 4 + 1) * 36 + kk];
        float a2 = As[(ty * 4 + 2) * 36 + kk];
        float a3 = As[(ty * 4 + 3) * 36 + kk];
        float4 w0 = *(const float4*)&Ws[kk * 128 + tx * 8];
        float4 w1 = *(const float4*)&Ws[kk * 128 + tx * 8 + 4];
        float wv[8] = {w0.x, w0.y, w0.z, w0.w, w1.x, w1.y, w1.z, w1.w};
#pragma unroll
        for (int c = 0; c < 8; c++) {
            acc[0][c] += a0 * wv[c];
            acc[1][c] += a1 * wv[c];
            acc[2][c] += a2 * wv[c];
            acc[3][c] += a3 * wv[c];
        }
    }
    const int col0 = tx * 8;
    float bb[8];
#pragma unroll
    for (int c = 0; c < 8; c++) bb[c] = __ldg(&b[col0 + c]);
#pragma unroll
    for (int r = 0; r < 4; r++) {
        int e = row0 + ty * 4 + r;
#pragma unroll
        for (int c = 0; c < 8; c++) g_edge_emb[e * 128 + col0 + c] = acc[r][c] + bb[c];
    }
}

// ---------------- fused edge message: gather + MLP(2x128x128) + atomic scatter ----------------
// msg_b2 is deferred (added in node update, gated by deg>0) — mathematically exact.
__global__ void __launch_bounds__(256) k_edge_msg(
    const float* __restrict__ W1, const float* __restrict__ b1,
    const float* __restrict__ W2)
{
    __shared__ float Ts[64 * 132];   // T tile, later reused as H tile
    __shared__ float Ws[16 * 128];
    __shared__ int   ss[64];
    const int tid = threadIdx.x;
    const int e0 = blockIdx.x * 64;

    if (tid < 64) ss[tid] = g_src[e0 + tid];
    __syncthreads();

    // T = node[src] + edge_emb
    for (int i = tid; i < 64 * 32; i += 256) {
        int r = i >> 5, q = i & 31;
        int s = ss[r];
        float4 nv = *(const float4*)&g_node[s * 128 + q * 4];
        float4 ev = *(const float4*)&g_edge_emb[(e0 + r) * 128 + q * 4];
        nv.x += ev.x; nv.y += ev.y; nv.z += ev.z; nv.w += ev.w;
        *(float4*)&Ts[r * 132 + q * 4] = nv;
    }

    const int tx = tid & 15, ty = tid >> 4;
    float acc[4][8];
#pragma unroll
    for (int r = 0; r < 4; r++)
#pragma unroll
        for (int c = 0; c < 8; c++) acc[r][c] = 0.f;

    // GEMM1: T @ W1
    for (int k0 = 0; k0 < 128; k0 += 16) {
        __syncthreads();
        for (int i = tid; i < 512; i += 256)
            ((float4*)Ws)[i] = ((const float4*)W1)[k0 * 32 + i];
        __syncthreads();
#pragma unroll
        for (int kk = 0; kk < 16; kk++) {
            float a0 = Ts[(ty * 4 + 0) * 132 + k0 + kk];
            float a1 = Ts[(ty * 4 + 1) * 132 + k0 + kk];
            float a2 = Ts[(ty * 4 + 2) * 132 + k0 + kk];
            float a3 = Ts[(ty * 4 + 3) * 132 + k0 + kk];
            float4 w0 = *(const float4*)&Ws[kk * 128 + tx * 8];
            float4 w1 = *(const float4*)&Ws[kk * 128 + tx * 8 + 4];
            float wv[8] = {w0.x, w0.y, w0.z, w0.w, w1.x, w1.y, w1.z, w1.w};
#pragma unroll
            for (int c = 0; c < 8; c++) {
                acc[0][c] += a0 * wv[c];
                acc[1][c] += a1 * wv[c];
                acc[2][c] += a2 * wv[c];
                acc[3][c] += a3 * wv[c];
            }
        }
    }

    // H = gelu(acc + b1) -> overwrite Ts
    const int col0 = tx * 8;
    float bb[8];
#pragma unroll
    for (int c = 0; c < 8; c++) bb[c] = __ldg(&b1[col0 + c]);
    __syncthreads();   // all reads of Ts done before overwrite
#pragma unroll
    for (int r = 0; r < 4; r++) {
        float h[8];
#pragma unroll
        for (int c = 0; c < 8; c++) h[c] = gelu_exact(acc[r][c] + bb[c]);
        *(float4*)&Ts[(ty * 4 + r) * 132 + col0]     = make_float4(h[0], h[1], h[2], h[3]);
        *(float4*)&Ts[(ty * 4 + r) * 132 + col0 + 4] = make_float4(h[4], h[5], h[6], h[7]);
    }

#pragma unroll
    for (int r = 0; r < 4; r++)
#pragma unroll
        for (int c = 0; c < 8; c++) acc[r][c] = 0.f;

    // GEMM2: H @ W2
    for (int k0 = 0; k0 < 128; k0 += 16) {
        __syncthreads();
        for (int i = tid; i < 512; i += 256)
            ((float4*)Ws)[i] = ((const float4*)W2)[k0 * 32 + i];
        __syncthreads();
#pragma unroll
        for (int kk = 0; kk < 16; kk++) {
            float a0 = Ts[(ty * 4 + 0) * 132 + k0 + kk];
            float a1 = Ts[(ty * 4 + 1) * 132 + k0 + kk];
            float a2 = Ts[(ty * 4 + 2) * 132 + k0 + kk];
            float a3 = Ts[(ty * 4 + 3) * 132 + k0 + kk];
            float4 w0 = *(const float4*)&Ws[kk * 128 + tx * 8];
            float4 w1 = *(const float4*)&Ws[kk * 128 + tx * 8 + 4];
            float wv[8] = {w0.x, w0.y, w0.z, w0.w, w1.x, w1.y, w1.z, w1.w};
#pragma unroll
            for (int c = 0; c < 8; c++) {
                acc[0][c] += a0 * wv[c];
                acc[1][c] += a1 * wv[c];
                acc[2][c] += a2 * wv[c];
                acc[3][c] += a3 * wv[c];
            }
        }
    }

    // scatter
#pragma unroll
    for (int r = 0; r < 4; r++) {
        int e = e0 + ty * 4 + r;
        int d = g_dst[e];
        float* dstp = &g_agg[d * 128 + col0];
#pragma unroll
        for (int c = 0; c < 8; c++) atomicAdd(&dstp[c], acc[r][c]);
    }
}

// ---------------- fused node update: agg/deg -> MLP(128->256->128) -> residual -> LN ----------------
__global__ void __launch_bounds__(256) k_node_upd(
    const float* __restrict__ W1, const float* __restrict__ b1,
    const float* __restrict__ W2, const float* __restrict__ b2,
    const float* __restrict__ mb2, const float* __restrict__ lng, const float* __restrict__ lnb)
{
    __shared__ float U[32 * 260];   // stage A: stride 132; stage U1: stride 260 (union)
    __shared__ float Ws[8 * 256];
    const int tid = threadIdx.x;
    const int n0 = blockIdx.x * 32;  // N % 32 == 0

    // A = agg * inv_deg + (deg>0) * msg_b2
    for (int i = tid; i < 32 * 32; i += 256) {
        int r = i >> 5, q = i & 31;
        int n = n0 + r;
        float id = g_invdeg[n];
        float gate = (g_deg[n] > 0) ? 1.f : 0.f;
        float4 v = *(const float4*)&g_agg[n * 128 + q * 4];
        float4 m = *(const float4*)&mb2[q * 4];
        v.x = v.x * id + gate * m.x;
        v.y = v.y * id + gate * m.y;
        v.z = v.z * id + gate * m.z;
        v.w = v.w * id + gate * m.w;
        *(float4*)&U[r * 132 + q * 4] = v;
    }

    // GEMM1: [32,128]@[128,256]; tx in 0..31 (8 cols each), ty in 0..7 (4 rows each)
    {
        const int tx = tid & 31, ty = tid >> 5;
        float acc[4][8];
#pragma unroll
        for (int r = 0; r < 4; r++)
#pragma unroll
            for (int c = 0; c < 8; c++) acc[r][c] = 0.f;

        for (int k0 = 0; k0 < 128; k0 += 8) {
            __syncthreads();
            for (int i = tid; i < 512; i += 256)
                ((float4*)Ws)[i] = ((const float4*)W1)[k0 * 64 + i];
            __syncthreads();
#pragma unroll
            for (int kk = 0; kk < 8; kk++) {
                float a0 = U[(ty * 4 + 0) * 132 + k0 + kk];
                float a1 = U[(ty * 4 + 1) * 132 + k0 + kk];
                float a2 = U[(ty * 4 + 2) * 132 + k0 + kk];
                float a3 = U[(ty * 4 + 3) * 132 + k0 + kk];
                float4 w0 = *(const float4*)&Ws[kk * 256 + tx * 8];
                float4 w1 = *(const float4*)&Ws[kk * 256 + tx * 8 + 4];
                float wv[8] = {w0.x, w0.y, w0.z, w0.w, w1.x, w1.y, w1.z, w1.w};
#pragma unroll
                for (int c = 0; c < 8; c++) {
                    acc[0][c] += a0 * wv[c];
                    acc[1][c] += a1 * wv[c];
                    acc[2][c] += a2 * wv[c];
                    acc[3][c] += a3 * wv[c];
                }
            }
        }
        const int col0 = tx * 8;
        float bb[8];
#pragma unroll
        for (int c = 0; c < 8; c++) bb[c] = __ldg(&b1[col0 + c]);
        __syncthreads();   // all A reads done before U1 overwrite
#pragma unroll
        for (int r = 0; r < 4; r++) {
            float h[8];
#pragma unroll
            for (int c = 0; c < 8; c++) h[c] = gelu_exact(acc[r][c] + bb[c]);
            *(float4*)&U[(ty * 4 + r) * 260 + col0]     = make_float4(h[0], h[1], h[2], h[3]);
            *(float4*)&U[(ty * 4 + r) * 260 + col0 + 4] = make_float4(h[4], h[5], h[6], h[7]);
        }
    }

    // GEMM2: [32,256]@[256,128]; tx2 in 0..15 (8 cols), ty2 in 0..15 (2 rows)
    {
        const int tx2 = tid & 15, ty2 = tid >> 4;
        float acc[2][8];
#pragma unroll
        for (int r = 0; r < 2; r++)
#pragma unroll
            for (int c = 0; c < 8; c++) acc[r][c] = 0.f;

        for (int k0 = 0; k0 < 256; k0 += 8) {
            __syncthreads();
            for (int i = tid; i < 256; i += 256)
                ((float4*)Ws)[i] = ((const float4*)W2)[k0 * 32 + i];
            __syncthreads();
#pragma unroll
            for (int kk = 0; kk < 8; kk++) {
                float a0 = U[(ty2 * 2 + 0) * 260 + k0 + kk];
                float a1 = U[(ty2 * 2 + 1) * 260 + k0 + kk];
                float4 w0 = *(const float4*)&Ws[kk * 128 + tx2 * 8];
                float4 w1 = *(const float4*)&Ws[kk * 128 + tx2 * 8 + 4];
                float wv[8] = {w0.x, w0.y, w0.z, w0.w, w1.x, w1.y, w1.z, w1.w};
#pragma unroll
                for (int c = 0; c < 8; c++) {
                    acc[0][c] += a0 * wv[c];
                    acc[1][c] += a1 * wv[c];
                }
            }
        }

        // residual + upd_b2, then LayerNorm per row (16 lanes per row, shfl reductions)
        const int col0 = tx2 * 8;
        float bb[8], gg[8], be[8];
#pragma unroll
        for (int c = 0; c < 8; c++) {
            bb[c] = __ldg(&b2[col0 + c]);
            gg[c] = __ldg(&lng[col0 + c]);
            be[c] = __ldg(&lnb[col0 + c]);
        }
#pragma unroll
        for (int r = 0; r < 2; r++) {
            int n = n0 + ty2 * 2 + r;
            float v[8];
            float4 o0 = *(const float4*)&g_node[n * 128 + col0];
            float4 o1 = *(const float4*)&g_node[n * 128 + col0 + 4];
            float ov[8] = {o0.x, o0.y, o0.z, o0.w, o1.x, o1.y, o1.z, o1.w};
            float s = 0.f;
#pragma unroll
            for (int c = 0; c < 8; c++) { v[c] = acc[r][c] + bb[c] + ov[c]; s += v[c]; }
#pragma unroll
            for (int o = 8; o > 0; o >>= 1) s += __shfl_xor_sync(0xffffffffu, s, o);
            float mean = s * (1.f / 128.f);
            float q = 0.f;
#pragma unroll
            for (int c = 0; c < 8; c++) { float d = v[c] - mean; q += d * d; }
#pragma unroll
            for (int o = 8; o > 0; o >>= 1) q += __shfl_xor_sync(0xffffffffu, q, o);
            float rs = rsqrtf(q * (1.f / 128.f) + EPSLN);
            float out[8];
#pragma unroll
            for (int c = 0; c < 8; c++) out[c] = (v[c] - mean) * rs * gg[c] + be[c];
            *(float4*)&g_node[n * 128 + col0]     = make_float4(out[0], out[1], out[2], out[3]);
            *(float4*)&g_node[n * 128 + col0 + 4] = make_float4(out[4], out[5], out[6], out[7]);
        }
    }
}

// ---------------- pooling ----------------
__global__ void __launch_bounds__(512) k_segsum() {
    const int j = blockIdx.x;              // 0..6
    const int start = j * 14286;
    const int end = min(NN, start + 14286);
    const int tid = threadIdx.x;
    const int d = tid & 127, part = tid >> 7;   // 4 partials per dim
    float s = 0.f;
    for (int n = start + part; n < end; n += 4) s += g_node[n * 128 + d];
    __shared__ float sh[512];
    sh[tid] = s;
    __syncthreads();
    if (part == 0) g_segsum[j * 128 + d] = sh[d] + sh[d + 128] + sh[d + 256] + sh[d + 384];
}

__device__ __forceinline__ float blockReduceSum128(float v) {
#pragma unroll
    for (int o = 16; o > 0; o >>= 1) v += __shfl_xor_sync(0xffffffffu, v, o);
    __shared__ float sh[4];
    int w = threadIdx.x >> 5;
    if ((threadIdx.x & 31) == 0) sh[w] = v;
    __syncthreads();
    float r = sh[0] + sh[1] + sh[2] + sh[3];
    __syncthreads();
    return r;
}

__global__ void __launch_bounds__(128) k_final(
    const float* __restrict__ og, const float* __restrict__ ob, float* __restrict__ out)
{
    const int t = threadIdx.x;
    __shared__ float st[8 * 128];
    float tot = 0.f;
#pragma unroll
    for (int j = 0; j < 7; j++) {
        float v = g_segsum[j * 128 + t];
        tot += v;
        float sz = (j < 6) ? 14286.f : 14284.f;
        st[(1 + j) * 128 + t] = v / sz;
    }
    st[t] = tot * (1.f / (float)NN);
    __syncthreads();
    for (int r = 0; r < 8; r++) {
        float xv = st[r * 128 + t];
        float mean = blockReduceSum128(xv) * (1.f / 128.f);
        float d = xv - mean;
        float var = blockReduceSum128(d * d) * (1.f / 128.f);
        out[r * 128 + t] = d * rsqrtf(var + EPSLN) * og[t] + ob[t];
    }
}

// ---------------- launcher ----------------
extern "C" void kernel_launch(void* const* d_in, const int* in_sizes, int n_in,
                              void* d_out, int out_size)
{
    const float* x      = (const float*)d_in[0];
    const void*  ei     = d_in[1];
    const float* ea     = (const float*)d_in[2];
    const float* node_w = (const float*)d_in[3];
    const float* node_b = (const float*)d_in[4];
    const float* edge_w = (const float*)d_in[5];
    const float* edge_b = (const float*)d_in[6];
    const float* msg_w1 = (const float*)d_in[7];
    const float* msg_b1 = (const float*)d_in[8];
    const float* msg_w2 = (const float*)d_in[9];
    const float* msg_b2 = (const float*)d_in[10];
    const float* upd_w1 = (const float*)d_in[11];
    const float* upd_b1 = (const float*)d_in[12];
    const float* upd_w2 = (const float*)d_in[13];
    const float* upd_b2 = (const float*)d_in[14];
    const float* ln_g   = (const float*)d_in[15];
    const float* ln_b   = (const float*)d_in[16];
    const float* out_g  = (const float*)d_in[17];
    const float* out_b  = (const float*)d_in[18];
    float* out = (float*)d_out;

    k_detect<<<1, 1>>>((const int*)ei);
    k_convert<<<(EE + 255) / 256, 256>>>(ei);
    k_zero_deg<<<(NN + 255) / 256, 256>>>();
    k_count_deg<<<(EE + 255) / 256, 256>>>();
    k_invdeg<<<(NN + 255) / 256, 256>>>();

    k_node_embed<<<(NN + 63) / 64, 256>>>(x, node_w, node_b);
    k_edge_embed<<<EE / 64, 256>>>(ea, edge_w, edge_b);

    for (int l = 0; l < 3; l++) {
        k_zero_agg<<<(NN * DD / 4 + 255) / 256, 256>>>();
        k_edge_msg<<<EE / 64, 256>>>(msg_w1 + l * 128 * 128, msg_b1 + l * 128,
                                     msg_w2 + l * 128 * 128);
        k_node_upd<<<NN / 32, 256>>>(upd_w1 + l * 128 * 256, upd_b1 + l * 256,
                                     upd_w2 + l * 256 * 128, upd_b2 + l * 128,
                                     msg_b2 + l * 128, ln_g + l * 128, ln_b + l * 128);
    }

    k_segsum<<<7, 512>>>();
    k_final<<<1, 128>>>(out_g, out_b, out);
}